// round 7
// baseline (speedup 1.0000x reference)
#include <cuda_runtime.h>
#include <cstddef>
#include <cstdint>

#define NB 64
#define NT 1024
#define NV 256
#define NS 256
#define ND 24
#define NL 513          // 2*NS+1
#define DGA 1344        // allocated dg rows per batch
#define EMW 264         // em row: [0]=blank, [2+j]=label j  (index 1 unused; 258 used, padded)
#define KPH 8           // steps per phase
#define NPH_S 163       // sdtw phases: 136 active + 9*3 lag
#define NPH_C 131       // ctc phases: 128 active + 3 lag
#define MLAG_S 9
#define GAMMA 0.1f
#define NEGF (-1e10f)
#define BIGF (1e10f)

// Scratch (no allocation allowed)
__device__ float g_pred[NB * NT * ND];            // predicted features (B,T,D)
__device__ float g_cost[(size_t)NB * DGA * NS];   // cost, [b][dg][j], dg=i+j+2 (0-based i,j)
__device__ float g_em[(size_t)NB * NT * EMW];     // emissions: blank + per-label
__device__ float g_loss[2 * NB];                  // [0..63] ctc, [64..127] sdtw

// mn <= md <= mx with pure min/max (no cancellation)
__device__ __forceinline__ void sort3(float a, float b, float c,
                                      float& mn, float& md, float& mx) {
    float t1 = fminf(a, b);
    float t2 = fmaxf(a, b);
    mn = fminf(t1, c);
    mx = fmaxf(t2, c);
    md = fmaxf(t1, fminf(t2, c));
}

// ----------------------------------------------------------------------------
// Kernel 1: pred = exp(log_probs) @ fm   (65536 x 256) @ (256 x 24)
// ----------------------------------------------------------------------------
__global__ __launch_bounds__(256) void prep_kernel(const float* __restrict__ lp,
                                                   const float* __restrict__ fm) {
    __shared__ float eS[64 * 129];
    __shared__ float fmS[64 * 25];

    const int tid = threadIdx.x;
    const int row0 = blockIdx.x * 128;
    const int rg = tid >> 3;
    const int dgrp = tid & 7;

    float acc[4][3];
#pragma unroll
    for (int i = 0; i < 4; i++)
#pragma unroll
        for (int j = 0; j < 3; j++) acc[i][j] = 0.f;

    for (int v0 = 0; v0 < NV; v0 += 64) {
        for (int idx = tid; idx < 64 * 24; idx += 256) {
            int v = idx / 24, d = idx - v * 24;
            fmS[v * 25 + d] = fm[(v0 + v) * ND + d];
        }
        for (int idx = tid; idx < 128 * 64; idx += 256) {
            int r = idx >> 6, v = idx & 63;
            eS[v * 129 + r] = __expf(lp[(size_t)(row0 + r) * NV + v0 + v]);
        }
        __syncthreads();

#pragma unroll 4
        for (int v = 0; v < 64; v++) {
            float e0 = eS[v * 129 + rg * 4 + 0];
            float e1 = eS[v * 129 + rg * 4 + 1];
            float e2 = eS[v * 129 + rg * 4 + 2];
            float e3 = eS[v * 129 + rg * 4 + 3];
            float f0 = fmS[v * 25 + dgrp * 3 + 0];
            float f1 = fmS[v * 25 + dgrp * 3 + 1];
            float f2 = fmS[v * 25 + dgrp * 3 + 2];
            acc[0][0] += e0 * f0; acc[0][1] += e0 * f1; acc[0][2] += e0 * f2;
            acc[1][0] += e1 * f0; acc[1][1] += e1 * f1; acc[1][2] += e1 * f2;
            acc[2][0] += e2 * f0; acc[2][1] += e2 * f1; acc[2][2] += e2 * f2;
            acc[3][0] += e3 * f0; acc[3][1] += e3 * f1; acc[3][2] += e3 * f2;
        }
        __syncthreads();
    }

#pragma unroll
    for (int i = 0; i < 4; i++)
#pragma unroll
        for (int j = 0; j < 3; j++)
            g_pred[(size_t)(row0 + rg * 4 + i) * ND + dgrp * 3 + j] = acc[i][j];
}

// ----------------------------------------------------------------------------
// Kernel 2: sdtw cost matrix, layout [b][dg][j], coalesced via diagonal rotation.
// ----------------------------------------------------------------------------
__global__ __launch_bounds__(256) void cost_kernel(const float* __restrict__ fm,
                                                   const int* __restrict__ targets) {
    __shared__ float predS[64 * 25];
    __shared__ float qS[256 * 25];
    __shared__ float pn[64];
    __shared__ float qn[256];
    __shared__ int qlab[256];

    const int tid = threadIdx.x;
    const int b = blockIdx.y;
    const int i0 = blockIdx.x * 64;

    qlab[tid] = targets[b * NS + tid];
    for (int idx = tid; idx < 64 * 24; idx += 256)
        predS[(idx / 24) * 25 + (idx % 24)] = g_pred[(size_t)(b * NT + i0) * ND + idx];
    __syncthreads();
    for (int idx = tid; idx < 256 * 24; idx += 256) {
        int c = idx / 24, d = idx - c * 24;
        qS[c * 25 + d] = fm[qlab[c] * ND + d];
    }
    __syncthreads();
    if (tid < 64) {
        float s = 0.f;
#pragma unroll
        for (int d = 0; d < ND; d++) { float x = predS[tid * 25 + d]; s += x * x; }
        pn[tid] = s;
    }
    {
        float s = 0.f;
#pragma unroll
        for (int d = 0; d < ND; d++) { float x = qS[tid * 25 + d]; s += x * x; }
        qn[tid] = s;
    }
    __syncthreads();

    const int w = tid >> 5;
    const int lane = tid & 31;
    const int j0 = w * 32;

    float p0[ND], p1[ND];
#pragma unroll
    for (int k = 0; k < ND; k++) {
        p0[k] = predS[lane * 25 + k];
        p1[k] = predS[(lane + 32) * 25 + k];
    }
    const float pn0 = pn[lane], pn1 = pn[lane + 32];
    const size_t cb = (size_t)b * DGA;
    const int D0 = i0 + j0 + 2;

#pragma unroll 4
    for (int c = 0; c < 32; c++) {
        int jc = j0 + ((c - lane) & 31);
        float dot0 = 0.f, dot1 = 0.f;
#pragma unroll
        for (int k = 0; k < ND; k++) {
            float q = qS[jc * 25 + k];
            dot0 += p0[k] * q;
            dot1 += p1[k] * q;
        }
        float qnj = qn[jc];
        int dg0 = D0 + c + ((lane > c) ? 32 : 0);
        g_cost[(cb + dg0) * NS + jc] = pn0 + qnj - 2.f * dot0;
        g_cost[(cb + dg0 + 32) * NS + jc] = pn1 + qnj - 2.f * dot1;
    }
}

// ----------------------------------------------------------------------------
// Kernel 3: emission table em[b][t][c]: c=0 -> blank lp[t][0], c=2+j -> lp[t][tgt[j]].
// (index 1 unused; labels start at even index so float2 loads are 8B-aligned)
// ----------------------------------------------------------------------------
__global__ __launch_bounds__(256) void em_kernel(const float* __restrict__ lp,
                                                 const int* __restrict__ targets) {
    __shared__ float rowS[256];
    __shared__ int tgtS[256];

    const int tid = threadIdx.x;
    const int b = blockIdx.x >> 4;
    const int t0 = (blockIdx.x & 15) << 6;

    tgtS[tid] = targets[b * NS + tid];
    const float* lpb = lp + ((size_t)b * NT + t0) * NV;
    float* emb = g_em + ((size_t)b * NT + t0) * EMW;
    __syncthreads();

    for (int tt = 0; tt < 64; tt++) {
        rowS[tid] = lpb[(size_t)tt * NV + tid];
        __syncthreads();
        emb[(size_t)tt * EMW + 2 + tid] = rowS[tgtS[tid]];
        if (tid == 0) emb[(size_t)tt * EMW] = rowS[0];
        __syncthreads();
    }
}

// ----------------------------------------------------------------------------
// Kernel 4 (fused DP, 4 warps/block, multi-cell threads, phase-skewed barriers):
//   blocks 0..63  -> soft-DTW : 2 cols/thread, K=8, lag m=9
//   blocks 64..127-> CTC      : 4 states/thread (+state 512 on last lane), lag m=1
// ----------------------------------------------------------------------------
__global__ __launch_bounds__(128) void main_kernel(const int* __restrict__ targets,
                                                   const int* __restrict__ in_len,
                                                   const int* __restrict__ tg_len) {
    __shared__ float bndR[4][1312];      // sdtw: lane31 (col 64w+64) history by dg
    __shared__ float ringT[4][32];       // ctc: lane31 A3 (state 128(w+1)-1), slot t&31
    __shared__ float actc[NL];

    const int tid = threadIdx.x;         // 0..127
    const int lane = tid & 31;
    const int w = tid >> 5;              // 0..3
    const int bid = blockIdx.x;

    if (bid < NB) {
        // ======================= soft-DTW =======================
        const int b = bid;
        const int jj0 = 2 * tid + 1;     // columns jj0, jj0+1 (1-based)
        const int s0 = 64 * w + 2;       // warp's first diagonal
        const float* cb = g_cost + (size_t)b * DGA * NS + 2 * tid;

        for (int idx = tid; idx < 4 * 1312; idx += 128) (&bndR[0][0])[idx] = BIGF;
        __syncthreads();

        float Rp0 = BIGF, Rp1 = BIGF;
        float r3c0 = (tid == 0) ? 0.f : BIGF;
        float r3c1 = BIGF;

        float2 buf0[KPH], buf1[KPH];
#pragma unroll
        for (int k = 0; k < KPH; k++) {
            buf0[k] = *(const float2*)(cb + (size_t)(s0 + k) * NS);
            buf1[k] = *(const float2*)(cb + (size_t)(s0 + KPH + k) * NS);
        }

        auto phaseS = [&](float2 (&bufc)[KPH], int stBase) {
#pragma unroll
            for (int k = 0; k < KPH; k++) {
                const int dg = s0 + stBase + k;
                float2 c = bufc[k];
                bufc[k] = *(const float2*)(cb + (size_t)(dg + 2 * KPH) * NS);
                float r2_0 = __shfl_up_sync(0xffffffffu, Rp1, 1);
                if (lane == 0) r2_0 = (w == 0) ? BIGF : bndR[w - 1][dg - 1];
                float r2_1 = Rp0;
                float mn, md, mx;
                sort3(Rp0, r2_0, r3c0, mn, md, mx);
                float sv0 = 1.f + __expf((mn - md) * 10.f) + __expf((mn - mx) * 10.f);
                const int i0 = dg - jj0;
                float Rn0 = (i0 >= 1 && i0 <= NT) ? (c.x + mn - GAMMA * __logf(sv0)) : BIGF;
                sort3(Rp1, r2_1, r3c1, mn, md, mx);
                float sv1 = 1.f + __expf((mn - md) * 10.f) + __expf((mn - mx) * 10.f);
                const int i1 = i0 - 1;
                float Rn1 = (i1 >= 1 && i1 <= NT) ? (c.y + mn - GAMMA * __logf(sv1)) : BIGF;
                if (lane == 31) bndR[w][dg] = Rn1;
                if (dg == NT + NS && tid == 127) g_loss[NB + b] = Rn1;
                r3c0 = r2_0; r3c1 = r2_1;
                Rp0 = Rn0; Rp1 = Rn1;
            }
        };

        int cur = 0;
        for (int p = 0; p < NPH_S; p++) {
            const int stBase = (p - MLAG_S * w) * KPH;
            if (stBase >= 0 && stBase <= 1080) {
                if (cur == 0) phaseS(buf0, stBase); else phaseS(buf1, stBase);
                cur ^= 1;
            }
            __syncthreads();
        }
    } else {
        // ======================= CTC forward =======================
        const int b = bid - NB;
        // thread tid owns states 4*tid .. 4*tid+3; lane31 of warp3 also state 512
        bool skip1 = false, skip3;
        {
            int t2k = targets[b * NS + 2 * tid];
            int t2k1 = targets[b * NS + 2 * tid + 1];
            skip3 = (t2k1 != t2k);
            if (tid > 0) skip1 = (t2k != targets[b * NS + 2 * tid - 1]);
        }
        const float* em = g_em + (size_t)b * NT * EMW;
        const float* emo = em + 2 + 2 * tid;     // odd-state emissions (labels 2k, 2k+1), 8B-aligned
        const int len = in_len[b];

        // t = 0 init
        float A0 = NEGF, A1 = NEGF, A2 = NEGF, A3 = NEGF, A4 = NEGF;
        if (tid == 0) { A0 = em[0]; A1 = em[2]; }
        if (lane == 31) ringT[w][0] = A3;
        __syncthreads();

        float2 buf0[KPH], buf1[KPH];
        float bb0[KPH], bb1[KPH];
#pragma unroll
        for (int k = 0; k < KPH; k++) {
            buf0[k] = *(const float2*)(emo + (size_t)(1 + k) * EMW);
            buf1[k] = *(const float2*)(emo + (size_t)(1 + KPH + k) * EMW);
            bb0[k] = em[(size_t)(1 + k) * EMW];
            bb1[k] = em[(size_t)(1 + KPH + k) * EMW];
        }

        auto phaseC = [&](float2 (&ebuf)[KPH], float (&bbuf)[KPH], int tBase) {
#pragma unroll
            for (int k = 0; k < KPH; k++) {
                const int t = tBase + k;
                float2 e = ebuf[k];
                float eb = bbuf[k];
                int tp = t + 2 * KPH; tp = (tp > NT - 1) ? (NT - 1) : tp;
                ebuf[k] = *(const float2*)(emo + (size_t)tp * EMW);
                bbuf[k] = em[(size_t)tp * EMW];
                float n3 = __shfl_up_sync(0xffffffffu, A3, 1);
                if (lane == 0) n3 = (w == 0) ? NEGF : ringT[w - 1][(t - 1) & 31];
                if (t < len) {
                    float mn, md, mx;
                    // s0 = 4k (even, blank-type): a2 = n3, a3 = NEG
                    float m0 = fmaxf(A0, n3);
                    float new0 = m0 + __logf(1.f + __expf(fminf(A0, n3) - m0)) + eb;
                    // s1 = 4k+1 (odd): a2 = A0, a3 = skip1 ? n3 : NEG
                    float a3v = skip1 ? n3 : NEGF;
                    sort3(A1, A0, a3v, mn, md, mx);
                    float new1 = mx + __logf(1.f + __expf(mn - mx) + __expf(md - mx)) + e.x;
                    // s2 = 4k+2 (even): a2 = A1
                    float m2 = fmaxf(A2, A1);
                    float new2 = m2 + __logf(1.f + __expf(fminf(A2, A1) - m2)) + eb;
                    // s3 = 4k+3 (odd): a2 = A2, a3 = skip3 ? A1 : NEG
                    float b3v = skip3 ? A1 : NEGF;
                    sort3(A3, A2, b3v, mn, md, mx);
                    float new3 = mx + __logf(1.f + __expf(mn - mx) + __expf(md - mx)) + e.y;
                    // s512 (even): a2 = A3 (state 511) — warp 3 lane 31 only
                    if (w == 3) {
                        float m4 = fmaxf(A4, A3);
                        float new4 = m4 + __logf(1.f + __expf(fminf(A4, A3) - m4)) + eb;
                        if (lane == 31) A4 = new4;
                    }
                    if (lane == 31) ringT[w][t & 31] = new3;
                    A0 = new0; A1 = new1; A2 = new2; A3 = new3;
                }
            }
        };

        int cur = 0;
        for (int p = 0; p < NPH_C; p++) {
            const int tBase = 1 + (p - w) * KPH;
            if (p >= w && tBase < len) {
                if (cur == 0) phaseC(buf0, bb0, tBase); else phaseC(buf1, bb1, tBase);
                cur ^= 1;
            }
            __syncthreads();
        }

        actc[4 * tid + 0] = A0;
        actc[4 * tid + 1] = A1;
        actc[4 * tid + 2] = A2;
        actc[4 * tid + 3] = A3;
        if (tid == 127) actc[512] = A4;
        __syncthreads();
        if (tid == 0) {
            int tl = tg_len[b];
            float aL = actc[2 * tl];
            float aP = actc[2 * tl - 1];
            float m = fmaxf(aL, aP);
            float ll = m + __logf(__expf(aL - m) + __expf(aP - m));
            g_loss[b] = -ll / (float)tl;
        }
    }
}

// ----------------------------------------------------------------------------
// Kernel 5: final reduction to scalar
// ----------------------------------------------------------------------------
__global__ void reduce_kernel(float* __restrict__ out) {
    const int tid = threadIdx.x;      // 128
    float v = g_loss[tid];
#pragma unroll
    for (int o = 16; o > 0; o >>= 1) v += __shfl_down_sync(0xffffffffu, v, o);
    __shared__ float ws[4];
    if ((tid & 31) == 0) ws[tid >> 5] = v;
    __syncthreads();
    if (tid == 0) out[0] = (ws[0] + ws[1] + ws[2] + ws[3]) * (1.f / (float)NB);
}

extern "C" void kernel_launch(void* const* d_in, const int* in_sizes, int n_in,
                              void* d_out, int out_size) {
    const float* lp  = (const float*)d_in[0];  // (B,T,V) f32
    const float* fm  = (const float*)d_in[1];  // (V,D)   f32
    const int*   tgt = (const int*)  d_in[2];  // (B,S)   i32
    const int*   il  = (const int*)  d_in[3];  // (B,)    i32
    const int*   tl  = (const int*)  d_in[4];  // (B,)    i32
    float* out = (float*)d_out;

    prep_kernel<<<512, 256>>>(lp, fm);
    em_kernel<<<1024, 256>>>(lp, tgt);
    cost_kernel<<<dim3(16, 64), 256>>>(fm, tgt);
    main_kernel<<<2 * NB, 128>>>(tgt, il, tl);
    reduce_kernel<<<1, 128>>>(out);
}

// round 8
// speedup vs baseline: 1.4572x; 1.4572x over previous
#include <cuda_runtime.h>
#include <cstddef>
#include <cstdint>

#define NB 64
#define NT 1024
#define NV 256
#define NS 256
#define ND 24
#define NL 513          // 2*NS+1
#define DGA 1344        // allocated dg rows per batch
#define EMW 260         // em row: [0..255]=labels, [256]=blank, pad to 260 (1040B, 16B-divisible)
#define KPH 8           // steps per phase
#define NPH_S 163       // sdtw phases: 136 active + 9*3 lag
#define NPH_C 131       // ctc phases: 128 active + 3 lag
#define MLAG_S 9
#define GAMMA 0.1f
#define NEGF (-1e10f)
#define BIGF (1e10f)

// Scratch (no allocation allowed)
__device__ float g_pred[NB * NT * ND];            // predicted features (B,T,D)
__device__ float g_cost[(size_t)NB * DGA * NS];   // cost, [b][dg][j], dg=i+j+2 (0-based i,j)
__device__ float g_em[(size_t)NB * NT * EMW];     // emissions per label + blank
__device__ float g_loss[2 * NB];                  // [0..63] ctc, [64..127] sdtw

// mn <= md <= mx with pure min/max (no cancellation)
__device__ __forceinline__ void sort3(float a, float b, float c,
                                      float& mn, float& md, float& mx) {
    float t1 = fminf(a, b);
    float t2 = fmaxf(a, b);
    mn = fminf(t1, c);
    mx = fmaxf(t2, c);
    md = fmaxf(t1, fminf(t2, c));
}

__device__ __forceinline__ void cpAsync16(uint32_t dst, const void* src) {
    asm volatile("cp.async.cg.shared.global [%0], [%1], 16;" :: "r"(dst), "l"(src));
}
__device__ __forceinline__ void cpAsync4(uint32_t dst, const void* src) {
    asm volatile("cp.async.ca.shared.global [%0], [%1], 4;" :: "r"(dst), "l"(src));
}
__device__ __forceinline__ void cpCommit() {
    asm volatile("cp.async.commit_group;" ::: "memory");
}
__device__ __forceinline__ void cpWait2() {
    asm volatile("cp.async.wait_group 2;" ::: "memory");
}

// ----------------------------------------------------------------------------
// Kernel 1: pred = exp(log_probs) @ fm   (65536 x 256) @ (256 x 24)
// ----------------------------------------------------------------------------
__global__ __launch_bounds__(256) void prep_kernel(const float* __restrict__ lp,
                                                   const float* __restrict__ fm) {
    __shared__ float eS[64 * 129];
    __shared__ float fmS[64 * 25];

    const int tid = threadIdx.x;
    const int row0 = blockIdx.x * 128;
    const int rg = tid >> 3;
    const int dgrp = tid & 7;

    float acc[4][3];
#pragma unroll
    for (int i = 0; i < 4; i++)
#pragma unroll
        for (int j = 0; j < 3; j++) acc[i][j] = 0.f;

    for (int v0 = 0; v0 < NV; v0 += 64) {
        for (int idx = tid; idx < 64 * 24; idx += 256) {
            int v = idx / 24, d = idx - v * 24;
            fmS[v * 25 + d] = fm[(v0 + v) * ND + d];
        }
        for (int idx = tid; idx < 128 * 64; idx += 256) {
            int r = idx >> 6, v = idx & 63;
            eS[v * 129 + r] = __expf(lp[(size_t)(row0 + r) * NV + v0 + v]);
        }
        __syncthreads();

#pragma unroll 4
        for (int v = 0; v < 64; v++) {
            float e0 = eS[v * 129 + rg * 4 + 0];
            float e1 = eS[v * 129 + rg * 4 + 1];
            float e2 = eS[v * 129 + rg * 4 + 2];
            float e3 = eS[v * 129 + rg * 4 + 3];
            float f0 = fmS[v * 25 + dgrp * 3 + 0];
            float f1 = fmS[v * 25 + dgrp * 3 + 1];
            float f2 = fmS[v * 25 + dgrp * 3 + 2];
            acc[0][0] += e0 * f0; acc[0][1] += e0 * f1; acc[0][2] += e0 * f2;
            acc[1][0] += e1 * f0; acc[1][1] += e1 * f1; acc[1][2] += e1 * f2;
            acc[2][0] += e2 * f0; acc[2][1] += e2 * f1; acc[2][2] += e2 * f2;
            acc[3][0] += e3 * f0; acc[3][1] += e3 * f1; acc[3][2] += e3 * f2;
        }
        __syncthreads();
    }

#pragma unroll
    for (int i = 0; i < 4; i++)
#pragma unroll
        for (int j = 0; j < 3; j++)
            g_pred[(size_t)(row0 + rg * 4 + i) * ND + dgrp * 3 + j] = acc[i][j];
}

// ----------------------------------------------------------------------------
// Kernel 2: sdtw cost matrix, layout [b][dg][j], coalesced via diagonal rotation.
// ----------------------------------------------------------------------------
__global__ __launch_bounds__(256) void cost_kernel(const float* __restrict__ fm,
                                                   const int* __restrict__ targets) {
    __shared__ float predS[64 * 25];
    __shared__ float qS[256 * 25];
    __shared__ float pn[64];
    __shared__ float qn[256];
    __shared__ int qlab[256];

    const int tid = threadIdx.x;
    const int b = blockIdx.y;
    const int i0 = blockIdx.x * 64;

    qlab[tid] = targets[b * NS + tid];
    for (int idx = tid; idx < 64 * 24; idx += 256)
        predS[(idx / 24) * 25 + (idx % 24)] = g_pred[(size_t)(b * NT + i0) * ND + idx];
    __syncthreads();
    for (int idx = tid; idx < 256 * 24; idx += 256) {
        int c = idx / 24, d = idx - c * 24;
        qS[c * 25 + d] = fm[qlab[c] * ND + d];
    }
    __syncthreads();
    if (tid < 64) {
        float s = 0.f;
#pragma unroll
        for (int d = 0; d < ND; d++) { float x = predS[tid * 25 + d]; s += x * x; }
        pn[tid] = s;
    }
    {
        float s = 0.f;
#pragma unroll
        for (int d = 0; d < ND; d++) { float x = qS[tid * 25 + d]; s += x * x; }
        qn[tid] = s;
    }
    __syncthreads();

    const int w = tid >> 5;
    const int lane = tid & 31;
    const int j0 = w * 32;

    float p0[ND], p1[ND];
#pragma unroll
    for (int k = 0; k < ND; k++) {
        p0[k] = predS[lane * 25 + k];
        p1[k] = predS[(lane + 32) * 25 + k];
    }
    const float pn0 = pn[lane], pn1 = pn[lane + 32];
    const size_t cb = (size_t)b * DGA;
    const int D0 = i0 + j0 + 2;

#pragma unroll 4
    for (int c = 0; c < 32; c++) {
        int jc = j0 + ((c - lane) & 31);
        float dot0 = 0.f, dot1 = 0.f;
#pragma unroll
        for (int k = 0; k < ND; k++) {
            float q = qS[jc * 25 + k];
            dot0 += p0[k] * q;
            dot1 += p1[k] * q;
        }
        float qnj = qn[jc];
        int dg0 = D0 + c + ((lane > c) ? 32 : 0);
        g_cost[(cb + dg0) * NS + jc] = pn0 + qnj - 2.f * dot0;
        g_cost[(cb + dg0 + 32) * NS + jc] = pn1 + qnj - 2.f * dot1;
    }
}

// ----------------------------------------------------------------------------
// Kernel 3: emission table em[b][t][j] = lp[t][tgt[j]] (j<256); em[b][t][256] = blank.
// ----------------------------------------------------------------------------
__global__ __launch_bounds__(256) void em_kernel(const float* __restrict__ lp,
                                                 const int* __restrict__ targets) {
    __shared__ float rowS[256];
    __shared__ int tgtS[256];

    const int tid = threadIdx.x;
    const int b = blockIdx.x >> 4;
    const int t0 = (blockIdx.x & 15) << 6;

    tgtS[tid] = targets[b * NS + tid];
    const float* lpb = lp + ((size_t)b * NT + t0) * NV;
    float* emb = g_em + ((size_t)b * NT + t0) * EMW;
    __syncthreads();

    for (int tt = 0; tt < 64; tt++) {
        rowS[tid] = lpb[(size_t)tt * NV + tid];
        __syncthreads();
        emb[(size_t)tt * EMW + tid] = rowS[tgtS[tid]];
        if (tid == 0) emb[(size_t)tt * EMW + 256] = rowS[0];
        __syncthreads();
    }
}

// ----------------------------------------------------------------------------
// Kernel 4 (fused DP, cp.async smem staging, phase-skewed barriers):
//   blocks 0..63  -> soft-DTW : 2 cols/thread, 4 warps, K=8, lag m=9
//   blocks 64..127-> CTC      : 4 states/thread, 4 warps, lag m=1
// Per-warp 3-deep smem ring of phase chunks staged via cp.async; serial DP
// reads LDS only — no LDG on the dependency chain.
// ----------------------------------------------------------------------------
#define STROW 68        // staged row: 64 data floats (+blank at [64] for ctc), padded
extern __shared__ float smf[];

__global__ __launch_bounds__(128) void main_kernel(const int* __restrict__ targets,
                                                   const int* __restrict__ in_len,
                                                   const int* __restrict__ tg_len) {
    float* stage = smf;                                  // [4][3][8][STROW]
    const int tid = threadIdx.x;                         // 0..127
    const int lane = tid & 31;
    const int w = tid >> 5;                              // 0..3
    const int bid = blockIdx.x;

    const uint32_t stageU =
        (uint32_t)__cvta_generic_to_shared(stage) + (uint32_t)(w * 3 * 8 * STROW) * 4u;
    const int rsel = lane >> 4;            // row parity this lane copies
    const int csel = lane & 15;            // 16B chunk within row

    if (bid < NB) {
        // ======================= soft-DTW =======================
        float* bndR = smf + 4 * 3 * 8 * STROW;           // [4][1312]
        const int b = bid;
        const int s0 = 64 * w + 2;                       // warp's first diagonal
        const int jj0 = 2 * tid + 1;                     // thread's first column (1-based)

        for (int idx = tid; idx < 4 * 1312; idx += 128) bndR[idx] = BIGF;

        auto stageS = [&](int buf, int dgStart) {
#pragma unroll
            for (int r = 0; r < 4; r++) {
                int row = 2 * r + rsel;
                int dgr = dgStart + row;
                dgr = (dgr < 0) ? 0 : ((dgr > DGA - 1) ? DGA - 1 : dgr);
                const float* src = g_cost + ((size_t)b * DGA + dgr) * NS + 64 * w + csel * 4;
                cpAsync16(stageU + (uint32_t)((buf * 8 + row) * STROW + csel * 4) * 4u, src);
            }
            cpCommit();
        };

        stageS(0, s0 + (0 - 9 * w) * KPH);
        stageS(1, s0 + (1 - 9 * w) * KPH);
        __syncthreads();                                 // bndR init visible

        float Rp0 = BIGF, Rp1 = BIGF;
        float r3c0 = (tid == 0) ? 0.f : BIGF;
        float r3c1 = BIGF;

        int buf = 0;
        for (int p = 0; p < NPH_S; p++) {
            int bufN = buf + 2; if (bufN >= 3) bufN -= 3;
            stageS(bufN, s0 + (p + 2 - 9 * w) * KPH);
            cpWait2();
            __syncwarp();
            const int stBase = (p - 9 * w) * KPH;
            if (stBase >= 0 && stBase <= 1080) {
                const float* rowB = stage + (w * 3 + buf) * 8 * STROW + 2 * lane;
#pragma unroll
                for (int k = 0; k < KPH; k++) {
                    const int dg = s0 + stBase + k;
                    float2 c = *(const float2*)(rowB + k * STROW);
                    float r2_0 = __shfl_up_sync(0xffffffffu, Rp1, 1);
                    if (lane == 0) r2_0 = (w == 0) ? BIGF : bndR[(w - 1) * 1312 + dg - 1];
                    float r2_1 = Rp0;
                    float mn, md, mx;
                    sort3(Rp0, r2_0, r3c0, mn, md, mx);
                    float sv0 = 1.f + __expf((mn - md) * 10.f) + __expf((mn - mx) * 10.f);
                    const int i0 = dg - jj0;
                    float Rn0 = (i0 >= 1 && i0 <= NT) ? (c.x + mn - GAMMA * __logf(sv0)) : BIGF;
                    sort3(Rp1, r2_1, r3c1, mn, md, mx);
                    float sv1 = 1.f + __expf((mn - md) * 10.f) + __expf((mn - mx) * 10.f);
                    const int i1 = i0 - 1;
                    float Rn1 = (i1 >= 1 && i1 <= NT) ? (c.y + mn - GAMMA * __logf(sv1)) : BIGF;
                    if (lane == 31) bndR[w * 1312 + dg] = Rn1;
                    if (dg == NT + NS && tid == 127) g_loss[NB + b] = Rn1;
                    r3c0 = r2_0; r3c1 = r2_1;
                    Rp0 = Rn0; Rp1 = Rn1;
                }
            }
            buf++; if (buf >= 3) buf -= 3;
            __syncthreads();
        }
    } else {
        // ======================= CTC forward =======================
        float* ringT = smf + 4 * 3 * 8 * STROW;          // [4][32]
        float* actc = ringT + 128;                        // [513]
        const int b = bid - NB;
        // thread tid owns states 4tid..4tid+3; w3/lane31 also state 512
        bool skip1 = false, skip3;
        {
            int t2k = targets[b * NS + 2 * tid];
            int t2k1 = targets[b * NS + 2 * tid + 1];
            skip3 = (t2k1 != t2k);
            if (tid > 0) skip1 = (t2k != targets[b * NS + 2 * tid - 1]);
        }
        const float* em = g_em + (size_t)b * NT * EMW;
        const int len = in_len[b];

        auto stageC = [&](int buf, int tStart) {
#pragma unroll
            for (int r = 0; r < 4; r++) {
                int row = 2 * r + rsel;
                int tr = tStart + row;
                tr = (tr < 0) ? 0 : ((tr > NT - 1) ? NT - 1 : tr);
                const float* src = em + (size_t)tr * EMW + 64 * w + csel * 4;
                cpAsync16(stageU + (uint32_t)((buf * 8 + row) * STROW + csel * 4) * 4u, src);
            }
            if (lane < 8) {                               // blank per row
                int tr = tStart + lane;
                tr = (tr < 0) ? 0 : ((tr > NT - 1) ? NT - 1 : tr);
                cpAsync4(stageU + (uint32_t)((buf * 8 + lane) * STROW + 64) * 4u,
                         em + (size_t)tr * EMW + 256);
            }
            cpCommit();
        };

        stageC(0, 1 + (0 - w) * KPH);
        stageC(1, 1 + (1 - w) * KPH);

        // t = 0 init
        float A0 = NEGF, A1 = NEGF, A2 = NEGF, A3 = NEGF, A4 = NEGF;
        if (tid == 0) { A0 = em[256]; A1 = em[0]; }
        if (lane == 31) ringT[w * 32] = A3;
        __syncthreads();

        int buf = 0;
        for (int p = 0; p < NPH_C; p++) {
            int bufN = buf + 2; if (bufN >= 3) bufN -= 3;
            stageC(bufN, 1 + (p + 2 - w) * KPH);
            cpWait2();
            __syncwarp();
            const int tBase = 1 + (p - w) * KPH;
            if (p >= w && tBase < len) {
                const float* rowB = stage + (w * 3 + buf) * 8 * STROW;
#pragma unroll
                for (int k = 0; k < KPH; k++) {
                    const int t = tBase + k;
                    float2 e = *(const float2*)(rowB + k * STROW + 2 * lane);
                    float eb = rowB[k * STROW + 64];
                    float n3 = __shfl_up_sync(0xffffffffu, A3, 1);
                    if (lane == 0) n3 = (w == 0) ? NEGF : ringT[(w - 1) * 32 + ((t - 1) & 31)];
                    if (t < len) {
                        float mn, md, mx;
                        // s0 = 4k (even): a2 = n3
                        float m0 = fmaxf(A0, n3);
                        float new0 = m0 + __logf(1.f + __expf(fminf(A0, n3) - m0)) + eb;
                        // s1 = 4k+1 (odd): a2 = A0, a3 = skip1 ? n3 : NEG
                        float a3v = skip1 ? n3 : NEGF;
                        sort3(A1, A0, a3v, mn, md, mx);
                        float new1 = mx + __logf(1.f + __expf(mn - mx) + __expf(md - mx)) + e.x;
                        // s2 = 4k+2 (even): a2 = A1
                        float m2 = fmaxf(A2, A1);
                        float new2 = m2 + __logf(1.f + __expf(fminf(A2, A1) - m2)) + eb;
                        // s3 = 4k+3 (odd): a2 = A2, a3 = skip3 ? A1 : NEG
                        float b3v = skip3 ? A1 : NEGF;
                        sort3(A3, A2, b3v, mn, md, mx);
                        float new3 = mx + __logf(1.f + __expf(mn - mx) + __expf(md - mx)) + e.y;
                        // s512 (even): a2 = A3 — warp 3 lane 31 only
                        if (w == 3) {
                            float m4 = fmaxf(A4, A3);
                            float new4 = m4 + __logf(1.f + __expf(fminf(A4, A3) - m4)) + eb;
                            if (lane == 31) A4 = new4;
                        }
                        if (lane == 31) ringT[w * 32 + (t & 31)] = new3;
                        A0 = new0; A1 = new1; A2 = new2; A3 = new3;
                    }
                }
            }
            buf++; if (buf >= 3) buf -= 3;
            __syncthreads();
        }

        actc[4 * tid + 0] = A0;
        actc[4 * tid + 1] = A1;
        actc[4 * tid + 2] = A2;
        actc[4 * tid + 3] = A3;
        if (tid == 127) actc[512] = A4;
        __syncthreads();
        if (tid == 0) {
            int tl = tg_len[b];
            float aL = actc[2 * tl];
            float aP = actc[2 * tl - 1];
            float m = fmaxf(aL, aP);
            float ll = m + __logf(__expf(aL - m) + __expf(aP - m));
            g_loss[b] = -ll / (float)tl;
        }
    }
}

// ----------------------------------------------------------------------------
// Kernel 5: final reduction to scalar
// ----------------------------------------------------------------------------
__global__ void reduce_kernel(float* __restrict__ out) {
    const int tid = threadIdx.x;      // 128
    float v = g_loss[tid];
#pragma unroll
    for (int o = 16; o > 0; o >>= 1) v += __shfl_down_sync(0xffffffffu, v, o);
    __shared__ float ws[4];
    if ((tid & 31) == 0) ws[tid >> 5] = v;
    __syncthreads();
    if (tid == 0) out[0] = (ws[0] + ws[1] + ws[2] + ws[3]) * (1.f / (float)NB);
}

extern "C" void kernel_launch(void* const* d_in, const int* in_sizes, int n_in,
                              void* d_out, int out_size) {
    const float* lp  = (const float*)d_in[0];  // (B,T,V) f32
    const float* fm  = (const float*)d_in[1];  // (V,D)   f32
    const int*   tgt = (const int*)  d_in[2];  // (B,S)   i32
    const int*   il  = (const int*)  d_in[3];  // (B,)    i32
    const int*   tl  = (const int*)  d_in[4];  // (B,)    i32
    float* out = (float*)d_out;

    // dynamic smem: stage 4*3*8*68 + bndR 4*1312 floats = 47104 B
    const int dynSmem = (4 * 3 * 8 * STROW + 4 * 1312) * 4;
    cudaFuncSetAttribute(main_kernel, cudaFuncAttributeMaxDynamicSharedMemorySize, dynSmem);

    prep_kernel<<<512, 256>>>(lp, fm);
    em_kernel<<<1024, 256>>>(lp, tgt);
    cost_kernel<<<dim3(16, 64), 256>>>(fm, tgt);
    main_kernel<<<2 * NB, 128, dynSmem>>>(tgt, il, tl);
    reduce_kernel<<<1, 128>>>(out);
}